// round 12
// baseline (speedup 1.0000x reference)
#include <cuda_runtime.h>
#include <cuda_bf16.h>
#include <math.h>

#define NPTS   8192
#define BATCH  4
#define K      16
#define TPB    128
#define LPQ    4                  // lanes per query
#define QPB    (TPB / LPQ)        // 32 queries per block
#define NG     16                 // cells per axis
#define NCELL  (NG*NG*NG)         // 4096
#define CLO    (-5.12f)
#define CW     (0.64f)

// ---------------- scratch (no allocs allowed) ----------------
__device__ float4 g_psort[BATCH * NPTS];   // sorted points: xyz + |p|^2
__device__ int    g_orig [BATCH * NPTS];   // sorted pos -> original index
__device__ int    g_cellid[BATCH * NPTS];
__device__ int    g_rank [BATCH * NPTS];
__device__ int    g_hist [BATCH * NCELL];  // counts
__device__ int    g_off  [BATCH * NCELL];  // exclusive offsets

__device__ __forceinline__ int morton3_4(int x, int y, int z) {
    int m = 0;
#pragma unroll
    for (int i = 0; i < 4; i++) {
        m |= (((x >> i) & 1) << (3 * i))
           | (((y >> i) & 1) << (3 * i + 1))
           | (((z >> i) & 1) << (3 * i + 2));
    }
    return m;
}

__device__ __forceinline__ int clampg(int v) {
    return v < 0 ? 0 : (v > NG - 1 ? NG - 1 : v);
}

// ---------------- pass 0: zero histograms ----------------
__global__ void zero_hist_kernel() {
    g_hist[blockIdx.x * 1024 + threadIdx.x] = 0;
}

// ---------------- pass 1: cell id + rank within cell ----------------
__global__ void cell_kernel(const float* __restrict__ x) {
    const int gi = blockIdx.x * blockDim.x + threadIdx.x;   // 0..B*N-1
    const int b  = gi / NPTS;
    const float px = x[gi * 3 + 0];
    const float py = x[gi * 3 + 1];
    const float pz = x[gi * 3 + 2];
    const float s = 1.0f / CW;
    const int ix = clampg((int)((px - CLO) * s));
    const int iy = clampg((int)((py - CLO) * s));
    const int iz = clampg((int)((pz - CLO) * s));
    const int cell = morton3_4(ix, iy, iz);
    const int r = atomicAdd(&g_hist[b * NCELL + cell], 1);
    g_cellid[gi] = cell;
    g_rank[gi] = r;
}

// ---------------- pass 2: exclusive scan of 4096 bins per batch ----------------
__global__ void scan_kernel() {
    __shared__ int s[1024];
    const int b = blockIdx.x, t = threadIdx.x;
    const int base = b * NCELL + t * 4;
    int v0 = g_hist[base + 0], v1 = g_hist[base + 1];
    int v2 = g_hist[base + 2], v3 = g_hist[base + 3];
    const int tot = v0 + v1 + v2 + v3;
    s[t] = tot;
    __syncthreads();
    for (int off = 1; off < 1024; off <<= 1) {
        int add = (t >= off) ? s[t - off] : 0;
        __syncthreads();
        s[t] += add;
        __syncthreads();
    }
    int run = s[t] - tot;
    g_off[base + 0] = run;  run += v0;
    g_off[base + 1] = run;  run += v1;
    g_off[base + 2] = run;  run += v2;
    g_off[base + 3] = run;
}

// ---------------- pass 3: scatter into Morton order ----------------
__global__ void scatter_kernel(const float* __restrict__ x) {
    const int gi = blockIdx.x * blockDim.x + threadIdx.x;
    const int b  = gi / NPTS;
    const int i  = gi - b * NPTS;
    const float px = x[gi * 3 + 0];
    const float py = x[gi * 3 + 1];
    const float pz = x[gi * 3 + 2];
    const int pos = g_off[b * NCELL + g_cellid[gi]] + g_rank[gi];
    g_psort[b * NPTS + pos] = make_float4(px, py, pz, px * px + py * py + pz * pz);
    g_orig [b * NPTS + pos] = i;
}

// ---------------- main kernel: 4-lane seeded shell kNN + eigen ----------------
__global__ __launch_bounds__(TPB)
void eig_ratio_kernel(float* __restrict__ out) {
    const int b     = blockIdx.y;
    const int tid   = threadIdx.x;
    const int phase = tid & (LPQ - 1);
    const int q     = blockIdx.x * QPB + (tid >> 2);   // sorted-order query pos
    const int bN    = b * NPTS;
    const int* __restrict__ offp = g_off  + b * NCELL;
    const int* __restrict__ cntp = g_hist + b * NCELL;

    const float4 qp = g_psort[bN + q];
    const float qx = qp.x, qy = qp.y, qz = qp.z, qsq = qp.w;
    const float s = 1.0f / CW;
    const int cx = clampg((int)((qx - CLO) * s));
    const int cy = clampg((int)((qy - CLO) * s));
    const int cz = clampg((int)((qz - CLO) * s));

    // ---- quad-cooperative seed threshold: max d2 over 16 window points ----
    int w = q - 8;
    if (w < 0) w = 0;
    if (w > NPTS - K) w = NPTS - K;
    float thresh0 = 0.0f;
#pragma unroll
    for (int t = 0; t < 4; t++) {
        const float4 c = g_psort[bN + w + phase * 4 + t];
        const float dot = qx * c.x + qy * c.y + qz * c.z;
        const float d2  = fmaf(-2.0f, dot, qsq + c.w);
        thresh0 = fmaxf(thresh0, d2);
    }
    thresh0 = fmaxf(thresh0, __shfl_xor_sync(0xFFFFFFFFu, thresh0, 1));
    thresh0 = fmaxf(thresh0, __shfl_xor_sync(0xFFFFFFFFu, thresh0, 2));

    float bval[K];
    int   bidx[K];
#pragma unroll
    for (int t = 0; t < K; t++) { bval[t] = 3.4e38f; bidx[t] = 0; }
    float worst = 3.4e38f;
    float cur   = thresh0;

    // lane scans every 4th point of each unpruned cell
    auto scan_cell = [&](int cellId) {
        const int beg = __ldg(offp + cellId);
        const int end = beg + __ldg(cntp + cellId);
#pragma unroll 2
        for (int j = beg + phase; j < end; j += LPQ) {
            const float4 c = g_psort[bN + j];
            const float dot = qx * c.x + qy * c.y + qz * c.z;
            const float d2  = fmaf(-2.0f, dot, qsq + c.w);
            if (d2 <= cur) {
                int ms = 0; float mv = bval[0];
#pragma unroll
                for (int t = 1; t < K; t++)
                    if (bval[t] > mv) { mv = bval[t]; ms = t; }
#pragma unroll
                for (int t = 0; t < K; t++)
                    if (t == ms) { bval[t] = d2; bidx[t] = j; }
                worst = bval[0];
#pragma unroll
                for (int t = 1; t < K; t++) worst = fmaxf(worst, bval[t]);
                cur = fminf(worst, thresh0);
            }
        }
    };

    // ring 0: own cell
    scan_cell(morton3_4(cx, cy, cz));

    // rings r = 1..NG-1 (Chebyshev shells); ring r is >= (r-1)*CW away
    // (edge cells extend to infinity, so this holds for clamped outliers).
    for (int r = 1; r <= NG - 1; r++) {
        const float ringmin = (float)(r - 1) * CW;
        if (ringmin * ringmin >= cur) break;
        for (int dz = -r; dz <= r; dz++) {
            const int iz = cz + dz;
            if ((unsigned)iz > (unsigned)(NG - 1)) continue;
            float lz = CLO + CW * iz, hz = lz + CW;
            if (iz == 0) lz = -1e30f;  if (iz == NG - 1) hz = 1e30f;
            const float ddz = fmaxf(fmaxf(lz - qz, qz - hz), 0.0f);
            const float zz = ddz * ddz;
            if (zz >= cur) continue;
            for (int dy = -r; dy <= r; dy++) {
                const int iy = cy + dy;
                if ((unsigned)iy > (unsigned)(NG - 1)) continue;
                const bool edge_zy = (dz == -r || dz == r || dy == -r || dy == r);
                float ly = CLO + CW * iy, hy = ly + CW;
                if (iy == 0) ly = -1e30f;  if (iy == NG - 1) hy = 1e30f;
                const float ddy = fmaxf(fmaxf(ly - qy, qy - hy), 0.0f);
                const float zy = zz + ddy * ddy;
                if (zy >= cur) continue;
                const int step = edge_zy ? 1 : 2 * r;
                for (int dx = -r; dx <= r; dx += step) {
                    const int ix = cx + dx;
                    if ((unsigned)ix > (unsigned)(NG - 1)) continue;
                    float lx = CLO + CW * ix, hx = lx + CW;
                    if (ix == 0) lx = -1e30f;  if (ix == NG - 1) hx = 1e30f;
                    const float ddx = fmaxf(fmaxf(lx - qx, qx - hx), 0.0f);
                    const float md2 = zy + ddx * ddx;
                    if (md2 >= cur) continue;
                    scan_cell(morton3_4(ix, iy, iz));
                }
            }
        }
    }

    // ---- bitonic full sort of local 16, ascending ----
#pragma unroll
    for (int k = 2; k <= K; k <<= 1) {
#pragma unroll
        for (int j = k >> 1; j > 0; j >>= 1) {
#pragma unroll
            for (int i = 0; i < K; i++) {
                const int l = i ^ j;
                if (l > i) {
                    const bool up = ((i & k) == 0);
                    if ((bval[i] > bval[l]) == up) {
                        float tv = bval[i]; bval[i] = bval[l]; bval[l] = tv;
                        int   ti = bidx[i]; bidx[i] = bidx[l]; bidx[l] = ti;
                    }
                }
            }
        }
    }

    // ---- merge 4 lanes' sorted-16 lists: 2 levels of bitonic min-merge ----
#pragma unroll
    for (int m = 1; m <= 2; m <<= 1) {
        float pv[K]; int pi[K];
#pragma unroll
        for (int t = 0; t < K; t++) {
            pv[t] = __shfl_xor_sync(0xFFFFFFFFu, bval[K - 1 - t], m);
            pi[t] = __shfl_xor_sync(0xFFFFFFFFu, bidx[K - 1 - t], m);
        }
#pragma unroll
        for (int t = 0; t < K; t++)
            if (pv[t] < bval[t]) { bval[t] = pv[t]; bidx[t] = pi[t]; }
        // bitonic cleanup -> ascending
#pragma unroll
        for (int j = K / 2; j > 0; j >>= 1) {
#pragma unroll
            for (int i = 0; i < K; i++) {
                const int l = i ^ j;
                if (l > i && bval[i] > bval[l]) {
                    float tv = bval[i]; bval[i] = bval[l]; bval[l] = tv;
                    int   ti = bidx[i]; bidx[i] = bidx[l]; bidx[l] = ti;
                }
            }
        }
    }

    if (phase != 0) return;

    // ---- gather neighbors, covariance (fp32, same as reference) ----
    float nx[K], ny[K], nz[K];
#pragma unroll
    for (int t = 0; t < K; t++) {
        const float4 np = g_psort[bN + bidx[t]];
        nx[t] = np.x; ny[t] = np.y; nz[t] = np.z;
    }
    float mx = 0.f, my = 0.f, mz = 0.f;
#pragma unroll
    for (int t = 0; t < K; t++) { mx += nx[t]; my += ny[t]; mz += nz[t]; }
    const float invk = 1.0f / (float)K;
    mx *= invk; my *= invk; mz *= invk;

    float c00 = 0.f, c01 = 0.f, c02 = 0.f, c11 = 0.f, c12 = 0.f, c22 = 0.f;
#pragma unroll
    for (int t = 0; t < K; t++) {
        const float dx = nx[t] - mx, dy = ny[t] - my, dz = nz[t] - mz;
        c00 += dx * dx; c01 += dx * dy; c02 += dx * dz;
        c11 += dy * dy; c12 += dy * dz; c22 += dz * dz;
    }

    // ---- 3x3 symmetric eigenvalues, trigonometric closed form (fp64) ----
    const double a00 = (double)(c00 * invk);
    const double a01 = (double)(c01 * invk);
    const double a02 = (double)(c02 * invk);
    const double a11 = (double)(c11 * invk);
    const double a12 = (double)(c12 * invk);
    const double a22 = (double)(c22 * invk);

    const double qm = (a00 + a11 + a22) / 3.0;
    const double p1 = a01 * a01 + a02 * a02 + a12 * a12;
    const double d0 = a00 - qm, d1 = a11 - qm, d2e = a22 - qm;
    const double p2 = d0 * d0 + d1 * d1 + d2e * d2e + 2.0 * p1;

    double ratio;
    if (p2 <= 0.0) {
        ratio = 1.0;
    } else {
        const double pp  = sqrt(p2 / 6.0);
        const double inv = 1.0 / pp;
        const double b00 = d0 * inv, b11 = d1 * inv, b22 = d2e * inv;
        const double b01 = a01 * inv, b02 = a02 * inv, b12 = a12 * inv;
        const double detB = b00 * (b11 * b22 - b12 * b12)
                          - b01 * (b01 * b22 - b12 * b02)
                          + b02 * (b01 * b12 - b11 * b02);
        double r = 0.5 * detB;
        r = fmin(1.0, fmax(-1.0, r));
        const double phi = acos(r) / 3.0;
        const double e_big   = qm + 2.0 * pp * cos(phi);
        const double e_small = qm + 2.0 * pp * cos(phi + 2.0943951023931953);
        const double e_mid   = 3.0 * qm - e_big - e_small;
        ratio = e_big / e_mid;
    }

    out[bN + g_orig[bN + q]] = (float)ratio;
}

extern "C" void kernel_launch(void* const* d_in, const int* in_sizes, int n_in,
                              void* d_out, int out_size) {
    const float* x = (const float*)d_in[0];   // (4, 8192, 3) fp32
    float* out = (float*)d_out;               // (4, 8192) fp32

    zero_hist_kernel<<<(BATCH * NCELL) / 1024, 1024>>>();
    cell_kernel<<<(BATCH * NPTS) / 256, 256>>>(x);
    scan_kernel<<<BATCH, 1024>>>();
    scatter_kernel<<<(BATCH * NPTS) / 256, 256>>>(x);

    dim3 grid(NPTS / QPB, BATCH);
    eig_ratio_kernel<<<grid, TPB>>>(out);
}

// round 13
// speedup vs baseline: 1.0161x; 1.0161x over previous
#include <cuda_runtime.h>
#include <cuda_bf16.h>
#include <math.h>

#define NPTS   8192
#define BATCH  4
#define K      16
#define TPB    128
#define LPQ    4                  // lanes per query
#define QPB    (TPB / LPQ)        // 32 queries per block
#define NG     16                 // cells per axis
#define NCELL  (NG*NG*NG)         // 4096
#define CLO    (-5.12f)
#define CW     (0.64f)

// ---------------- scratch (no allocs allowed) ----------------
__device__ float4 g_psort[BATCH * NPTS];   // sorted points: xyz + |p|^2
__device__ int    g_orig [BATCH * NPTS];   // sorted pos -> original index
__device__ int    g_cellid[BATCH * NPTS];
__device__ int    g_rank [BATCH * NPTS];
__device__ int    g_hist [BATCH * NCELL];  // counts
__device__ int    g_off  [BATCH * NCELL];  // exclusive offsets

__device__ __forceinline__ int morton3_4(int x, int y, int z) {
    int m = 0;
#pragma unroll
    for (int i = 0; i < 4; i++) {
        m |= (((x >> i) & 1) << (3 * i))
           | (((y >> i) & 1) << (3 * i + 1))
           | (((z >> i) & 1) << (3 * i + 2));
    }
    return m;
}

__device__ __forceinline__ int clampg(int v) {
    return v < 0 ? 0 : (v > NG - 1 ? NG - 1 : v);
}

// ---------------- pass 0: zero histograms ----------------
__global__ void zero_hist_kernel() {
    g_hist[blockIdx.x * 1024 + threadIdx.x] = 0;
}

// ---------------- pass 1: cell id + rank within cell ----------------
__global__ void cell_kernel(const float* __restrict__ x) {
    const int gi = blockIdx.x * blockDim.x + threadIdx.x;   // 0..B*N-1
    const int b  = gi / NPTS;
    const float px = x[gi * 3 + 0];
    const float py = x[gi * 3 + 1];
    const float pz = x[gi * 3 + 2];
    const float s = 1.0f / CW;
    const int ix = clampg((int)((px - CLO) * s));
    const int iy = clampg((int)((py - CLO) * s));
    const int iz = clampg((int)((pz - CLO) * s));
    const int cell = morton3_4(ix, iy, iz);
    const int r = atomicAdd(&g_hist[b * NCELL + cell], 1);
    g_cellid[gi] = cell;
    g_rank[gi] = r;
}

// ---------------- pass 2: exclusive scan of 4096 bins per batch ----------------
__global__ void scan_kernel() {
    __shared__ int s[1024];
    const int b = blockIdx.x, t = threadIdx.x;
    const int base = b * NCELL + t * 4;
    int v0 = g_hist[base + 0], v1 = g_hist[base + 1];
    int v2 = g_hist[base + 2], v3 = g_hist[base + 3];
    const int tot = v0 + v1 + v2 + v3;
    s[t] = tot;
    __syncthreads();
    for (int off = 1; off < 1024; off <<= 1) {
        int add = (t >= off) ? s[t - off] : 0;
        __syncthreads();
        s[t] += add;
        __syncthreads();
    }
    int run = s[t] - tot;
    g_off[base + 0] = run;  run += v0;
    g_off[base + 1] = run;  run += v1;
    g_off[base + 2] = run;  run += v2;
    g_off[base + 3] = run;
}

// ---------------- pass 3: scatter into Morton order ----------------
__global__ void scatter_kernel(const float* __restrict__ x) {
    const int gi = blockIdx.x * blockDim.x + threadIdx.x;
    const int b  = gi / NPTS;
    const int i  = gi - b * NPTS;
    const float px = x[gi * 3 + 0];
    const float py = x[gi * 3 + 1];
    const float pz = x[gi * 3 + 2];
    const int pos = g_off[b * NCELL + g_cellid[gi]] + g_rank[gi];
    g_psort[b * NPTS + pos] = make_float4(px, py, pz, px * px + py * py + pz * pz);
    g_orig [b * NPTS + pos] = i;
}

// ---------------- main kernel: 4-lane seeded shell kNN + eigen ----------------
__global__ __launch_bounds__(TPB)
void eig_ratio_kernel(float* __restrict__ out) {
    const int b     = blockIdx.y;
    const int tid   = threadIdx.x;
    const int phase = tid & (LPQ - 1);
    const int q     = blockIdx.x * QPB + (tid >> 2);   // sorted-order query pos
    const int bN    = b * NPTS;
    const int* __restrict__ offp = g_off  + b * NCELL;
    const int* __restrict__ cntp = g_hist + b * NCELL;

    const float4 qp = g_psort[bN + q];
    const float qx = qp.x, qy = qp.y, qz = qp.z, qsq = qp.w;
    const float s = 1.0f / CW;
    const int cx = clampg((int)((qx - CLO) * s));
    const int cy = clampg((int)((qy - CLO) * s));
    const int cz = clampg((int)((qz - CLO) * s));

    // ---- quad-cooperative seed threshold: max d2 over 16 window points ----
    int w = q - 8;
    if (w < 0) w = 0;
    if (w > NPTS - K) w = NPTS - K;
    float thresh0 = 0.0f;
#pragma unroll
    for (int t = 0; t < 4; t++) {
        const float4 c = g_psort[bN + w + phase * 4 + t];
        const float dot = qx * c.x + qy * c.y + qz * c.z;
        const float d2  = fmaf(-2.0f, dot, qsq + c.w);
        thresh0 = fmaxf(thresh0, d2);
    }
    thresh0 = fmaxf(thresh0, __shfl_xor_sync(0xFFFFFFFFu, thresh0, 1));
    thresh0 = fmaxf(thresh0, __shfl_xor_sync(0xFFFFFFFFu, thresh0, 2));

    float bval[K];
    int   bidx[K];
#pragma unroll
    for (int t = 0; t < K; t++) { bval[t] = 3.4e38f; bidx[t] = 0; }
    float worst = 3.4e38f;
    float cur   = thresh0;

    // lane scans every 4th point of each unpruned cell
    auto scan_cell = [&](int cellId) {
        const int beg = __ldg(offp + cellId);
        const int end = beg + __ldg(cntp + cellId);
#pragma unroll 2
        for (int j = beg + phase; j < end; j += LPQ) {
            const float4 c = g_psort[bN + j];
            const float dot = qx * c.x + qy * c.y + qz * c.z;
            const float d2  = fmaf(-2.0f, dot, qsq + c.w);
            if (d2 <= cur) {
                int ms = 0; float mv = bval[0];
#pragma unroll
                for (int t = 1; t < K; t++)
                    if (bval[t] > mv) { mv = bval[t]; ms = t; }
#pragma unroll
                for (int t = 0; t < K; t++)
                    if (t == ms) { bval[t] = d2; bidx[t] = j; }
                worst = bval[0];
#pragma unroll
                for (int t = 1; t < K; t++) worst = fmaxf(worst, bval[t]);
                cur = fminf(worst, thresh0);
            }
        }
    };

    // ring 0: own cell
    scan_cell(morton3_4(cx, cy, cz));

    // rings r = 1..NG-1 (Chebyshev shells); ring r is >= (r-1)*CW away
    // (edge cells extend to infinity, so this holds for clamped outliers).
    for (int r = 1; r <= NG - 1; r++) {
        const float ringmin = (float)(r - 1) * CW;
        if (ringmin * ringmin >= cur) break;
        for (int dz = -r; dz <= r; dz++) {
            const int iz = cz + dz;
            if ((unsigned)iz > (unsigned)(NG - 1)) continue;
            float lz = CLO + CW * iz, hz = lz + CW;
            if (iz == 0) lz = -1e30f;  if (iz == NG - 1) hz = 1e30f;
            const float ddz = fmaxf(fmaxf(lz - qz, qz - hz), 0.0f);
            const float zz = ddz * ddz;
            if (zz >= cur) continue;
            for (int dy = -r; dy <= r; dy++) {
                const int iy = cy + dy;
                if ((unsigned)iy > (unsigned)(NG - 1)) continue;
                const bool edge_zy = (dz == -r || dz == r || dy == -r || dy == r);
                float ly = CLO + CW * iy, hy = ly + CW;
                if (iy == 0) ly = -1e30f;  if (iy == NG - 1) hy = 1e30f;
                const float ddy = fmaxf(fmaxf(ly - qy, qy - hy), 0.0f);
                const float zy = zz + ddy * ddy;
                if (zy >= cur) continue;
                const int step = edge_zy ? 1 : 2 * r;
                for (int dx = -r; dx <= r; dx += step) {
                    const int ix = cx + dx;
                    if ((unsigned)ix > (unsigned)(NG - 1)) continue;
                    float lx = CLO + CW * ix, hx = lx + CW;
                    if (ix == 0) lx = -1e30f;  if (ix == NG - 1) hx = 1e30f;
                    const float ddx = fmaxf(fmaxf(lx - qx, qx - hx), 0.0f);
                    const float md2 = zy + ddx * ddx;
                    if (md2 >= cur) continue;
                    scan_cell(morton3_4(ix, iy, iz));
                }
            }
        }
    }

    // ---- bitonic full sort of local 16, ascending ----
#pragma unroll
    for (int k = 2; k <= K; k <<= 1) {
#pragma unroll
        for (int j = k >> 1; j > 0; j >>= 1) {
#pragma unroll
            for (int i = 0; i < K; i++) {
                const int l = i ^ j;
                if (l > i) {
                    const bool up = ((i & k) == 0);
                    if ((bval[i] > bval[l]) == up) {
                        float tv = bval[i]; bval[i] = bval[l]; bval[l] = tv;
                        int   ti = bidx[i]; bidx[i] = bidx[l]; bidx[l] = ti;
                    }
                }
            }
        }
    }

    // ---- merge 4 lanes' sorted-16 lists: 2 levels of bitonic min-merge ----
#pragma unroll
    for (int m = 1; m <= 2; m <<= 1) {
        float pv[K]; int pi[K];
#pragma unroll
        for (int t = 0; t < K; t++) {
            pv[t] = __shfl_xor_sync(0xFFFFFFFFu, bval[K - 1 - t], m);
            pi[t] = __shfl_xor_sync(0xFFFFFFFFu, bidx[K - 1 - t], m);
        }
#pragma unroll
        for (int t = 0; t < K; t++)
            if (pv[t] < bval[t]) { bval[t] = pv[t]; bidx[t] = pi[t]; }
        // bitonic cleanup -> ascending
#pragma unroll
        for (int j = K / 2; j > 0; j >>= 1) {
#pragma unroll
            for (int i = 0; i < K; i++) {
                const int l = i ^ j;
                if (l > i && bval[i] > bval[l]) {
                    float tv = bval[i]; bval[i] = bval[l]; bval[l] = tv;
                    int   ti = bidx[i]; bidx[i] = bidx[l]; bidx[l] = ti;
                }
            }
        }
    }

    if (phase != 0) return;

    // ---- gather neighbors, covariance (fp32, same as reference) ----
    float nx[K], ny[K], nz[K];
#pragma unroll
    for (int t = 0; t < K; t++) {
        const float4 np = g_psort[bN + bidx[t]];
        nx[t] = np.x; ny[t] = np.y; nz[t] = np.z;
    }
    float mx = 0.f, my = 0.f, mz = 0.f;
#pragma unroll
    for (int t = 0; t < K; t++) { mx += nx[t]; my += ny[t]; mz += nz[t]; }
    const float invk = 1.0f / (float)K;
    mx *= invk; my *= invk; mz *= invk;

    float c00 = 0.f, c01 = 0.f, c02 = 0.f, c11 = 0.f, c12 = 0.f, c22 = 0.f;
#pragma unroll
    for (int t = 0; t < K; t++) {
        const float dx = nx[t] - mx, dy = ny[t] - my, dz = nz[t] - mz;
        c00 += dx * dx; c01 += dx * dy; c02 += dx * dz;
        c11 += dy * dy; c12 += dy * dz; c22 += dz * dz;
    }

    // ---- 3x3 symmetric eigenvalues, trigonometric closed form (fp64) ----
    const double a00 = (double)(c00 * invk);
    const double a01 = (double)(c01 * invk);
    const double a02 = (double)(c02 * invk);
    const double a11 = (double)(c11 * invk);
    const double a12 = (double)(c12 * invk);
    const double a22 = (double)(c22 * invk);

    const double qm = (a00 + a11 + a22) / 3.0;
    const double p1 = a01 * a01 + a02 * a02 + a12 * a12;
    const double d0 = a00 - qm, d1 = a11 - qm, d2e = a22 - qm;
    const double p2 = d0 * d0 + d1 * d1 + d2e * d2e + 2.0 * p1;

    double ratio;
    if (p2 <= 0.0) {
        ratio = 1.0;
    } else {
        const double pp  = sqrt(p2 / 6.0);
        const double inv = 1.0 / pp;
        const double b00 = d0 * inv, b11 = d1 * inv, b22 = d2e * inv;
        const double b01 = a01 * inv, b02 = a02 * inv, b12 = a12 * inv;
        const double detB = b00 * (b11 * b22 - b12 * b12)
                          - b01 * (b01 * b22 - b12 * b02)
                          + b02 * (b01 * b12 - b11 * b02);
        double r = 0.5 * detB;
        r = fmin(1.0, fmax(-1.0, r));
        const double phi = acos(r) / 3.0;
        const double e_big   = qm + 2.0 * pp * cos(phi);
        const double e_small = qm + 2.0 * pp * cos(phi + 2.0943951023931953);
        const double e_mid   = 3.0 * qm - e_big - e_small;
        ratio = e_big / e_mid;
    }

    out[bN + g_orig[bN + q]] = (float)ratio;
}

extern "C" void kernel_launch(void* const* d_in, const int* in_sizes, int n_in,
                              void* d_out, int out_size) {
    const float* x = (const float*)d_in[0];   // (4, 8192, 3) fp32
    float* out = (float*)d_out;               // (4, 8192) fp32

    zero_hist_kernel<<<(BATCH * NCELL) / 1024, 1024>>>();
    cell_kernel<<<(BATCH * NPTS) / 256, 256>>>(x);
    scan_kernel<<<BATCH, 1024>>>();
    scatter_kernel<<<(BATCH * NPTS) / 256, 256>>>(x);

    dim3 grid(NPTS / QPB, BATCH);
    eig_ratio_kernel<<<grid, TPB>>>(out);
}

// round 14
// speedup vs baseline: 1.0221x; 1.0060x over previous
#include <cuda_runtime.h>
#include <cuda_bf16.h>
#include <math.h>

#define NPTS   8192
#define BATCH  4
#define K      16
#define TPB    128
#define LPQ    4                  // lanes per query
#define QPB    (TPB / LPQ)        // 32 queries per block
#define NG     16                 // cells per axis
#define NCELL  (NG*NG*NG)         // 4096
#define CLO    (-5.12f)
#define CW     (0.64f)

// ---------------- scratch (no allocs allowed) ----------------
__device__ float4 g_psort[BATCH * NPTS];   // sorted points: xyz + |p|^2
__device__ int    g_orig [BATCH * NPTS];   // sorted pos -> original index
__device__ int    g_cellid[BATCH * NPTS];
__device__ int    g_rank [BATCH * NPTS];
__device__ int    g_hist [BATCH * NCELL];  // counts
__device__ int    g_off  [BATCH * NCELL];  // exclusive offsets

__device__ __forceinline__ int morton3_4(int x, int y, int z) {
    int m = 0;
#pragma unroll
    for (int i = 0; i < 4; i++) {
        m |= (((x >> i) & 1) << (3 * i))
           | (((y >> i) & 1) << (3 * i + 1))
           | (((z >> i) & 1) << (3 * i + 2));
    }
    return m;
}

__device__ __forceinline__ int clampg(int v) {
    return v < 0 ? 0 : (v > NG - 1 ? NG - 1 : v);
}

// ---------------- pass 0: zero histograms ----------------
__global__ void zero_hist_kernel() {
    g_hist[blockIdx.x * 1024 + threadIdx.x] = 0;
}

// ---------------- pass 1: cell id + rank within cell ----------------
__global__ void cell_kernel(const float* __restrict__ x) {
    const int gi = blockIdx.x * blockDim.x + threadIdx.x;   // 0..B*N-1
    const int b  = gi / NPTS;
    const float px = x[gi * 3 + 0];
    const float py = x[gi * 3 + 1];
    const float pz = x[gi * 3 + 2];
    const float s = 1.0f / CW;
    const int ix = clampg((int)((px - CLO) * s));
    const int iy = clampg((int)((py - CLO) * s));
    const int iz = clampg((int)((pz - CLO) * s));
    const int cell = morton3_4(ix, iy, iz);
    const int r = atomicAdd(&g_hist[b * NCELL + cell], 1);
    g_cellid[gi] = cell;
    g_rank[gi] = r;
}

// ---------------- pass 2: exclusive scan of 4096 bins per batch ----------------
__global__ void scan_kernel() {
    __shared__ int s[1024];
    const int b = blockIdx.x, t = threadIdx.x;
    const int base = b * NCELL + t * 4;
    int v0 = g_hist[base + 0], v1 = g_hist[base + 1];
    int v2 = g_hist[base + 2], v3 = g_hist[base + 3];
    const int tot = v0 + v1 + v2 + v3;
    s[t] = tot;
    __syncthreads();
    for (int off = 1; off < 1024; off <<= 1) {
        int add = (t >= off) ? s[t - off] : 0;
        __syncthreads();
        s[t] += add;
        __syncthreads();
    }
    int run = s[t] - tot;
    g_off[base + 0] = run;  run += v0;
    g_off[base + 1] = run;  run += v1;
    g_off[base + 2] = run;  run += v2;
    g_off[base + 3] = run;
}

// ---------------- pass 3: scatter into Morton order ----------------
__global__ void scatter_kernel(const float* __restrict__ x) {
    const int gi = blockIdx.x * blockDim.x + threadIdx.x;
    const int b  = gi / NPTS;
    const int i  = gi - b * NPTS;
    const float px = x[gi * 3 + 0];
    const float py = x[gi * 3 + 1];
    const float pz = x[gi * 3 + 2];
    const int pos = g_off[b * NCELL + g_cellid[gi]] + g_rank[gi];
    g_psort[b * NPTS + pos] = make_float4(px, py, pz, px * px + py * py + pz * pz);
    g_orig [b * NPTS + pos] = i;
}

// ---------------- main kernel: 4-lane seeded shell kNN + eigen ----------------
__global__ __launch_bounds__(TPB)
void eig_ratio_kernel(float* __restrict__ out) {
    const int b     = blockIdx.y;
    const int tid   = threadIdx.x;
    const int phase = tid & (LPQ - 1);
    const int q     = blockIdx.x * QPB + (tid >> 2);   // sorted-order query pos
    const int bN    = b * NPTS;
    const int* __restrict__ offp = g_off  + b * NCELL;
    const int* __restrict__ cntp = g_hist + b * NCELL;

    const float4 qp = g_psort[bN + q];
    const float qx = qp.x, qy = qp.y, qz = qp.z, qsq = qp.w;
    const float s = 1.0f / CW;
    const int cx = clampg((int)((qx - CLO) * s));
    const int cy = clampg((int)((qy - CLO) * s));
    const int cz = clampg((int)((qz - CLO) * s));

    // ---- quad-cooperative seed threshold: max d2 over 16 window points ----
    int w = q - 8;
    if (w < 0) w = 0;
    if (w > NPTS - K) w = NPTS - K;
    float thresh0 = 0.0f;
#pragma unroll
    for (int t = 0; t < 4; t++) {
        const float4 c = g_psort[bN + w + phase * 4 + t];
        const float dot = qx * c.x + qy * c.y + qz * c.z;
        const float d2  = fmaf(-2.0f, dot, qsq + c.w);
        thresh0 = fmaxf(thresh0, d2);
    }
    thresh0 = fmaxf(thresh0, __shfl_xor_sync(0xFFFFFFFFu, thresh0, 1));
    thresh0 = fmaxf(thresh0, __shfl_xor_sync(0xFFFFFFFFu, thresh0, 2));

    float bval[K];
    int   bidx[K];
#pragma unroll
    for (int t = 0; t < K; t++) { bval[t] = 3.4e38f; bidx[t] = 0; }
    float worst = 3.4e38f;
    float cur   = thresh0;

    // lane scans every 4th point of each unpruned cell
    auto scan_cell = [&](int cellId) {
        const int beg = __ldg(offp + cellId);
        const int end = beg + __ldg(cntp + cellId);
#pragma unroll 2
        for (int j = beg + phase; j < end; j += LPQ) {
            const float4 c = g_psort[bN + j];
            const float dot = qx * c.x + qy * c.y + qz * c.z;
            const float d2  = fmaf(-2.0f, dot, qsq + c.w);
            if (d2 <= cur) {
                int ms = 0; float mv = bval[0];
#pragma unroll
                for (int t = 1; t < K; t++)
                    if (bval[t] > mv) { mv = bval[t]; ms = t; }
#pragma unroll
                for (int t = 0; t < K; t++)
                    if (t == ms) { bval[t] = d2; bidx[t] = j; }
                worst = bval[0];
#pragma unroll
                for (int t = 1; t < K; t++) worst = fmaxf(worst, bval[t]);
                cur = fminf(worst, thresh0);
            }
        }
    };

    // ring 0: own cell
    scan_cell(morton3_4(cx, cy, cz));

    // rings r = 1..NG-1 (Chebyshev shells); ring r is >= (r-1)*CW away
    // (edge cells extend to infinity, so this holds for clamped outliers).
    for (int r = 1; r <= NG - 1; r++) {
        const float ringmin = (float)(r - 1) * CW;
        if (ringmin * ringmin >= cur) break;
        for (int dz = -r; dz <= r; dz++) {
            const int iz = cz + dz;
            if ((unsigned)iz > (unsigned)(NG - 1)) continue;
            float lz = CLO + CW * iz, hz = lz + CW;
            if (iz == 0) lz = -1e30f;  if (iz == NG - 1) hz = 1e30f;
            const float ddz = fmaxf(fmaxf(lz - qz, qz - hz), 0.0f);
            const float zz = ddz * ddz;
            if (zz >= cur) continue;
            for (int dy = -r; dy <= r; dy++) {
                const int iy = cy + dy;
                if ((unsigned)iy > (unsigned)(NG - 1)) continue;
                const bool edge_zy = (dz == -r || dz == r || dy == -r || dy == r);
                float ly = CLO + CW * iy, hy = ly + CW;
                if (iy == 0) ly = -1e30f;  if (iy == NG - 1) hy = 1e30f;
                const float ddy = fmaxf(fmaxf(ly - qy, qy - hy), 0.0f);
                const float zy = zz + ddy * ddy;
                if (zy >= cur) continue;
                const int step = edge_zy ? 1 : 2 * r;
                for (int dx = -r; dx <= r; dx += step) {
                    const int ix = cx + dx;
                    if ((unsigned)ix > (unsigned)(NG - 1)) continue;
                    float lx = CLO + CW * ix, hx = lx + CW;
                    if (ix == 0) lx = -1e30f;  if (ix == NG - 1) hx = 1e30f;
                    const float ddx = fmaxf(fmaxf(lx - qx, qx - hx), 0.0f);
                    const float md2 = zy + ddx * ddx;
                    if (md2 >= cur) continue;
                    scan_cell(morton3_4(ix, iy, iz));
                }
            }
        }
    }

    // ---- bitonic full sort of local 16, ascending ----
#pragma unroll
    for (int k = 2; k <= K; k <<= 1) {
#pragma unroll
        for (int j = k >> 1; j > 0; j >>= 1) {
#pragma unroll
            for (int i = 0; i < K; i++) {
                const int l = i ^ j;
                if (l > i) {
                    const bool up = ((i & k) == 0);
                    if ((bval[i] > bval[l]) == up) {
                        float tv = bval[i]; bval[i] = bval[l]; bval[l] = tv;
                        int   ti = bidx[i]; bidx[i] = bidx[l]; bidx[l] = ti;
                    }
                }
            }
        }
    }

    // ---- merge 4 lanes' sorted-16 lists: 2 levels of bitonic min-merge ----
#pragma unroll
    for (int m = 1; m <= 2; m <<= 1) {
        float pv[K]; int pi[K];
#pragma unroll
        for (int t = 0; t < K; t++) {
            pv[t] = __shfl_xor_sync(0xFFFFFFFFu, bval[K - 1 - t], m);
            pi[t] = __shfl_xor_sync(0xFFFFFFFFu, bidx[K - 1 - t], m);
        }
#pragma unroll
        for (int t = 0; t < K; t++)
            if (pv[t] < bval[t]) { bval[t] = pv[t]; bidx[t] = pi[t]; }
        // bitonic cleanup -> ascending
#pragma unroll
        for (int j = K / 2; j > 0; j >>= 1) {
#pragma unroll
            for (int i = 0; i < K; i++) {
                const int l = i ^ j;
                if (l > i && bval[i] > bval[l]) {
                    float tv = bval[i]; bval[i] = bval[l]; bval[l] = tv;
                    int   ti = bidx[i]; bidx[i] = bidx[l]; bidx[l] = ti;
                }
            }
        }
    }

    if (phase != 0) return;

    // ---- gather neighbors, covariance (fp32, same as reference) ----
    float nx[K], ny[K], nz[K];
#pragma unroll
    for (int t = 0; t < K; t++) {
        const float4 np = g_psort[bN + bidx[t]];
        nx[t] = np.x; ny[t] = np.y; nz[t] = np.z;
    }
    float mx = 0.f, my = 0.f, mz = 0.f;
#pragma unroll
    for (int t = 0; t < K; t++) { mx += nx[t]; my += ny[t]; mz += nz[t]; }
    const float invk = 1.0f / (float)K;
    mx *= invk; my *= invk; mz *= invk;

    float c00 = 0.f, c01 = 0.f, c02 = 0.f, c11 = 0.f, c12 = 0.f, c22 = 0.f;
#pragma unroll
    for (int t = 0; t < K; t++) {
        const float dx = nx[t] - mx, dy = ny[t] - my, dz = nz[t] - mz;
        c00 += dx * dx; c01 += dx * dy; c02 += dx * dz;
        c11 += dy * dy; c12 += dy * dz; c22 += dz * dz;
    }

    // ---- 3x3 symmetric eigenvalues, trigonometric closed form (fp64) ----
    const double a00 = (double)(c00 * invk);
    const double a01 = (double)(c01 * invk);
    const double a02 = (double)(c02 * invk);
    const double a11 = (double)(c11 * invk);
    const double a12 = (double)(c12 * invk);
    const double a22 = (double)(c22 * invk);

    const double qm = (a00 + a11 + a22) / 3.0;
    const double p1 = a01 * a01 + a02 * a02 + a12 * a12;
    const double d0 = a00 - qm, d1 = a11 - qm, d2e = a22 - qm;
    const double p2 = d0 * d0 + d1 * d1 + d2e * d2e + 2.0 * p1;

    double ratio;
    if (p2 <= 0.0) {
        ratio = 1.0;
    } else {
        const double pp  = sqrt(p2 / 6.0);
        const double inv = 1.0 / pp;
        const double b00 = d0 * inv, b11 = d1 * inv, b22 = d2e * inv;
        const double b01 = a01 * inv, b02 = a02 * inv, b12 = a12 * inv;
        const double detB = b00 * (b11 * b22 - b12 * b12)
                          - b01 * (b01 * b22 - b12 * b02)
                          + b02 * (b01 * b12 - b11 * b02);
        double r = 0.5 * detB;
        r = fmin(1.0, fmax(-1.0, r));
        const double phi = acos(r) / 3.0;
        const double e_big   = qm + 2.0 * pp * cos(phi);
        const double e_small = qm + 2.0 * pp * cos(phi + 2.0943951023931953);
        const double e_mid   = 3.0 * qm - e_big - e_small;
        ratio = e_big / e_mid;
    }

    out[bN + g_orig[bN + q]] = (float)ratio;
}

extern "C" void kernel_launch(void* const* d_in, const int* in_sizes, int n_in,
                              void* d_out, int out_size) {
    const float* x = (const float*)d_in[0];   // (4, 8192, 3) fp32
    float* out = (float*)d_out;               // (4, 8192) fp32

    zero_hist_kernel<<<(BATCH * NCELL) / 1024, 1024>>>();
    cell_kernel<<<(BATCH * NPTS) / 256, 256>>>(x);
    scan_kernel<<<BATCH, 1024>>>();
    scatter_kernel<<<(BATCH * NPTS) / 256, 256>>>(x);

    dim3 grid(NPTS / QPB, BATCH);
    eig_ratio_kernel<<<grid, TPB>>>(out);
}